// round 1
// baseline (speedup 1.0000x reference)
#include <cuda_runtime.h>
#include <math.h>

#define NB     8
#define CFEAT  384
#define CCODE  90
#define CPAD   96
#define HH     56
#define WW     56
#define SSD    32
#define SP     1024      // 32*32 spatial positions
#define NCOMBO 40        // 5 perms * 8 batch
#define HWIMG  (HH*WW)   // 3136

// ---------------- scratch (device globals; no allocation allowed) ----------------
__device__ float g_F1[NB][CFEAT*SP];       // normalized feats @ c1   [c][s]
__device__ float g_F2[NCOMBO][CFEAT*SP];   // normalized permuted feats @ c2
__device__ float g_LP[NB][CPAD*SP];        // log_softmax(code @ c1)  [c][s], pad zeros
__device__ float g_Q1[NB][CPAD*SP];        // exp(LP)                 pad zeros
__device__ float g_Q2[NCOMBO][CPAD*SP];    // softmax(code_neg @ c2)  pad zeros
__device__ float g_E1[NB][SP];             // entropy terms sum(q*lq)
__device__ float g_E2[NCOMBO][SP];
__device__ double g_acc[2];                // [0]=pos sum, [1]=neg sum

// ---------------- bilinear helper (border pad, align_corners=True) ----------------
struct BI { int o00,o01,o10,o11; float w00,w01,w10,w11; };

__device__ __forceinline__ BI bilinear(const float* __restrict__ crd) {
    float gx = (crd[0] + 1.0f) * 0.5f * (float)(WW-1);
    float gy = (crd[1] + 1.0f) * 0.5f * (float)(HH-1);
    gx = fminf(fmaxf(gx, 0.0f), (float)(WW-1));
    gy = fminf(fmaxf(gy, 0.0f), (float)(HH-1));
    float x0f = floorf(gx), y0f = floorf(gy);
    float wx = gx - x0f,   wy = gy - y0f;
    int x0 = (int)x0f, y0 = (int)y0f;
    int x1 = min(x0+1, WW-1), y1 = min(y0+1, HH-1);
    BI b;
    b.o00 = y0*WW + x0; b.o01 = y0*WW + x1;
    b.o10 = y1*WW + x0; b.o11 = y1*WW + x1;
    b.w00 = (1.0f-wx)*(1.0f-wy); b.w01 = wx*(1.0f-wy);
    b.w10 = (1.0f-wx)*wy;        b.w11 = wx*wy;
    return b;
}

// grid-sample feats for one (image, coord-set) and L2-normalize along channels
__device__ __forceinline__ void sample_norm_feats(const float* __restrict__ img,
                                                  const float* __restrict__ crd,
                                                  float* __restrict__ out, int s) {
    BI bi = bilinear(crd);
    float ss = 0.0f;
    #pragma unroll 4
    for (int c = 0; c < CFEAT; ++c) {
        const float* p = img + c*HWIMG;
        float v = bi.w00*p[bi.o00] + bi.w01*p[bi.o01] + bi.w10*p[bi.o10] + bi.w11*p[bi.o11];
        ss += v*v;
        out[c*SP + s] = v;
    }
    float sc = 1.0f / fmaxf(sqrtf(ss), 1e-10f);
    #pragma unroll 4
    for (int c = 0; c < CFEAT; ++c) out[c*SP + s] *= sc;
}

__device__ __forceinline__ void sample_code_raw(const float* __restrict__ img,
                                                const float* __restrict__ crd,
                                                float* __restrict__ out, int s) {
    BI bi = bilinear(crd);
    #pragma unroll 2
    for (int c = 0; c < CCODE; ++c) {
        const float* p = img + c*HWIMG;
        float v = bi.w00*p[bi.o00] + bi.w01*p[bi.o01] + bi.w10*p[bi.o10] + bi.w11*p[bi.o11];
        out[c*SP + s] = v;
    }
}

// ---------------- kernels ----------------
__global__ void k_init() { g_acc[0] = 0.0; g_acc[1] = 0.0; }

// A-side: 8 batches, coords1 transposed (output (a,b) uses coords1[n][b][a])
__global__ void k_sample_A(const float* __restrict__ feats,
                           const float* __restrict__ code,
                           const float* __restrict__ coords1) {
    int blk = blockIdx.x;            // 0..31
    int n = blk >> 2;
    int s = ((blk & 3) << 8) + threadIdx.x;
    int a = s >> 5, b = s & 31;
    const float* crd = coords1 + (((n*SSD + b)*SSD + a) << 1);
    sample_norm_feats(feats + (size_t)n*CFEAT*HWIMG, crd, g_F1[n], s);
    sample_code_raw (code  + (size_t)n*CCODE*HWIMG, crd, g_LP[n], s);
}

// B-side: 40 combos (perm k, batch i): image perms[k*8+i], coords2[i]
__global__ void k_sample_B(const float* __restrict__ feats,
                           const float* __restrict__ code,
                           const float* __restrict__ coords2,
                           const int*   __restrict__ perms) {
    int blk = blockIdx.x;            // 0..159
    int combo = blk >> 2;
    int i = combo & 7;
    int p = perms[combo];
    int s = ((blk & 3) << 8) + threadIdx.x;
    int a = s >> 5, b = s & 31;
    const float* crd = coords2 + (((i*SSD + b)*SSD + a) << 1);
    sample_norm_feats(feats + (size_t)p*CFEAT*HWIMG, crd, g_F2[combo], s);
    sample_code_raw (code  + (size_t)p*CCODE*HWIMG, crd, g_Q2[combo], s);
}

// column-wise log-softmax on raw code values; writes lp (optional), q, entropy
__device__ __forceinline__ void softmax_col(float* __restrict__ raw,  // in: raw, out: lp or q
                                            float* __restrict__ qout, // may equal raw
                                            float* __restrict__ entp,
                                            int s, bool keep_lp) {
    float m = -1e30f;
    for (int c = 0; c < CCODE; ++c) m = fmaxf(m, raw[c*SP + s]);
    float se = 0.0f;
    for (int c = 0; c < CCODE; ++c) se += expf(raw[c*SP + s] - m);
    float ls = m + logf(se);
    float ent = 0.0f;
    for (int c = 0; c < CCODE; ++c) {
        float l = raw[c*SP + s] - ls;
        float q = expf(l);
        ent += q * l;
        if (keep_lp) raw[c*SP + s] = l;
        qout[c*SP + s] = q;
    }
    for (int c = CCODE; c < CPAD; ++c) {              // zero pad channels
        if (keep_lp) raw[c*SP + s] = 0.0f;
        qout[c*SP + s] = 0.0f;
    }
    entp[s] = ent;
}

__global__ void k_softmax_A() {
    int blk = blockIdx.x; int n = blk >> 2;
    int s = ((blk & 3) << 8) + threadIdx.x;
    softmax_col(g_LP[n], g_Q1[n], g_E1[n], s, true);
}

__global__ void k_softmax_B() {
    int blk = blockIdx.x; int combo = blk >> 2;
    int s = ((blk & 3) << 8) + threadIdx.x;
    softmax_col(g_Q2[combo], g_Q2[combo], g_E2[combo], s, false);
}

// ---------------- fused dual-GEMM + epilogue + reduce ----------------
__device__ __forceinline__ void mm_acc(const float* __restrict__ A,
                                       const float* __restrict__ B,
                                       int Ktot, int m0, int n0,
                                       int tid, int tx, int ty,
                                       float acc[4][4],
                                       float (*As)[64], float (*Bs)[64]) {
    for (int k0 = 0; k0 < Ktot; k0 += 16) {
        #pragma unroll
        for (int r = 0; r < 4; ++r) {
            int e  = tid + (r << 8);
            int kr = e >> 6, cm = e & 63;
            As[kr][cm] = A[(k0 + kr)*SP + m0 + cm];
            Bs[kr][cm] = B[(k0 + kr)*SP + n0 + cm];
        }
        __syncthreads();
        #pragma unroll
        for (int kk = 0; kk < 16; ++kk) {
            float4 a = *(const float4*)&As[kk][tx << 2];
            float4 b = *(const float4*)&Bs[kk][ty << 2];
            float av[4] = {a.x, a.y, a.z, a.w};
            float bv[4] = {b.x, b.y, b.z, b.w};
            #pragma unroll
            for (int mi = 0; mi < 4; ++mi)
                #pragma unroll
                for (int jj = 0; jj < 4; ++jj)
                    acc[mi][jj] += av[mi] * bv[jj];
        }
        __syncthreads();
    }
}

__global__ void __launch_bounds__(256) k_gemm_loss() {
    __shared__ float As[16][64];
    __shared__ float Bs[16][64];
    __shared__ float red[8];

    int pair = blockIdx.z;
    int m0 = blockIdx.x * 64, n0 = blockIdx.y * 64;
    const float *Af, *Bf, *Alp, *Bq, *entp;
    if (pair < 8) {
        Af = g_F1[pair]; Bf = g_F1[pair];
        Alp = g_LP[pair]; Bq = g_Q1[pair]; entp = g_E1[pair];
    } else {
        int c = pair - 8; int i = c & 7;
        Af = g_F1[i]; Bf = g_F2[c];
        Alp = g_LP[i]; Bq = g_Q2[c]; entp = g_E2[c];
    }

    int tid = threadIdx.x;
    int tx = tid & 15, ty = tid >> 4;

    float fd[4][4], cr[4][4];
    #pragma unroll
    for (int i = 0; i < 4; ++i)
        #pragma unroll
        for (int j = 0; j < 4; ++j) { fd[i][j] = 0.0f; cr[i][j] = 0.0f; }

    mm_acc(Af,  Bf, CFEAT, m0, n0, tid, tx, ty, fd, As, Bs);  // cosine sim, K=384
    mm_acc(Alp, Bq, CPAD,  m0, n0, tid, tx, ty, cr, As, Bs);  // cross term, K=96

    float e[4];
    #pragma unroll
    for (int jj = 0; jj < 4; ++jj) e[jj] = entp[n0 + (ty << 2) + jj];

    // loss = (fd - cd)^2, cd = -tanh(0.5*(ent - cross - 1.1))
    float lsum = 0.0f;
    #pragma unroll
    for (int mi = 0; mi < 4; ++mi)
        #pragma unroll
        for (int jj = 0; jj < 4; ++jj) {
            float t = e[jj] - cr[mi][jj] - 1.1f;
            t = fminf(fmaxf(t, -30.0f), 30.0f);
            float u  = __expf(t);                       // tanh(t/2) = (e^t-1)/(e^t+1)
            float th = __fdividef(u - 1.0f, u + 1.0f);
            float d  = fd[mi][jj] + th;
            lsum += d * d;
        }

    // block reduce
    #pragma unroll
    for (int off = 16; off > 0; off >>= 1)
        lsum += __shfl_down_sync(0xffffffffu, lsum, off);
    if ((tid & 31) == 0) red[tid >> 5] = lsum;
    __syncthreads();
    if (tid == 0) {
        float tot = 0.0f;
        #pragma unroll
        for (int w = 0; w < 8; ++w) tot += red[w];
        atomicAdd(&g_acc[pair < 8 ? 0 : 1], (double)tot);
    }
}

__global__ void k_finalize(float* __restrict__ out) {
    out[0] = (float)(g_acc[0] / (double)(8.0  * 1024.0 * 1024.0 * 1024.0 / 1024.0 * 1024.0) );
    // careful: compute explicitly below instead
}

__global__ void k_finalize2(float* __restrict__ out) {
    out[0] = (float)(g_acc[0] / 8388608.0);    // 8  * 1024 * 1024
    out[1] = (float)(g_acc[1] / 41943040.0);   // 40 * 1024 * 1024
}

// ---------------- launch ----------------
extern "C" void kernel_launch(void* const* d_in, const int* in_sizes, int n_in,
                              void* d_out, int out_size) {
    const float* feats   = (const float*)d_in[0];
    const float* code    = (const float*)d_in[1];
    const float* coords1 = (const float*)d_in[2];
    const float* coords2 = (const float*)d_in[3];
    const int*   perms   = (const int*)  d_in[4];
    float* out = (float*)d_out;

    k_init<<<1, 1>>>();
    k_sample_A<<<32, 256>>>(feats, code, coords1);
    k_softmax_A<<<32, 256>>>();
    k_sample_B<<<160, 256>>>(feats, code, coords2, perms);
    k_softmax_B<<<160, 256>>>();
    dim3 g(16, 16, 48);
    k_gemm_loss<<<g, 256>>>();
    k_finalize2<<<1, 1>>>(out);
}